// round 2
// baseline (speedup 1.0000x reference)
#include <cuda_runtime.h>
#include <cuda_bf16.h>

// AdEx neuron sim, sm_103a.
// 4 neurons per thread (float4 I/O), T-loop in-kernel, state in registers.
// UNROLL=8 timesteps, double-buffered prefetch -> 8 LDG.128 in flight/thread.
// exp folded to a single MUFU.EX2: K*exp(a) = 2^(a*log2e + log2K).

#define UNROLL 8

// ---- compile-time constants (from reference module) ----
#define C_EL        (-70.6e-3f)
#define C_VT        (-50.4e-3f)
#define C_INVDELT   (500.0f)                    // 1/DELTAT
#define C_VT500     (25.2f)                     // -VT/DELTAT
#define C_DTCM      (3558718.8612099644f)       // DT/CM
#define C_A1        (0.8932384341670107f)       // 1 - DT/CM*GL
#define C_CADD      (-0.007537366548042705f)    // DT/CM*GL*EL
#define C_LOG2E     (1.4426950408889634f)
#define C_LOG2KE    (-12.19360729f)             // log2(DT/CM * GL * DELTAT)
#define C_CC        (0.9930555555555556f)       // 1 - DT/TAUW
#define C_CA        (2.7777777777777777e-11f)   // DT/TAUW * A
#define C_CB        (1.9611111111111113e-12f)   // -DT/TAUW * A * EL
#define C_B         (0.0805e-9f)
#define C_REFSTEPS  2

__device__ __forceinline__ float fast_exp_scaled(float arg) {
    // returns (DT/CM)*GL*DELTAT * exp(arg)
    float y = fmaf(arg, C_LOG2E, C_LOG2KE);
    float e;
    asm("ex2.approx.ftz.f32 %0, %1;" : "=f"(e) : "f"(y));
    return e;
}

// One AdEx step for a single neuron; writes v_out, updates state in place.
__device__ __forceinline__ void adex_step(float It, float& v, float& c, int& ref,
                                          float& v_out) {
    bool  in_ref = ref > 0;
    float v_eff  = in_ref ? C_EL : v;

    float arg = fminf(fmaf(v_eff, C_INVDELT, C_VT500), 15.0f);
    float e   = fast_exp_scaled(arg);           // scaled exp term

    // v_new = A1*v_eff + CADD + DT_CM*It - DT_CM*c + e
    float p = fmaf(C_DTCM, It, C_CADD);
    float q = fmaf(-C_DTCM, c, p);
    float v_new = fmaf(C_A1, v_eff, q + e);
    v_new = in_ref ? C_EL : v_new;

    // c_new = CC*c + CA*v_eff + CB
    float c_new = fmaf(C_CC, c, fmaf(C_CA, v_eff, C_CB));

    bool spike = v_new >= C_VT;
    v   = spike ? C_EL : v_new;
    c   = spike ? (c_new + C_B) : c_new;
    ref = spike ? C_REFSTEPS : max(ref - 1, 0);
    v_out = v;
}

__global__ void __launch_bounds__(64) adex_vec4_kernel(
    const float4* __restrict__ I,    // [T, N4]
    const float4* __restrict__ v0,
    const float4* __restrict__ c0,
    const int4*   __restrict__ ref0,
    float4*       __restrict__ out,  // [T, N4]
    int T, int N4)
{
    int n = blockIdx.x * blockDim.x + threadIdx.x;
    if (n >= N4) return;

    float4 v4 = v0[n];
    float4 c4 = c0[n];
    int4   r4 = ref0[n];

    float vv[4] = {v4.x, v4.y, v4.z, v4.w};
    float cc[4] = {c4.x, c4.y, c4.z, c4.w};
    int   rr[4] = {r4.x, r4.y, r4.z, r4.w};

    const float4* Ip = I + n;
    float4*       Op = out + n;

    int Tm = (T / UNROLL) * UNROLL;

    float4 buf[UNROLL];
    #pragma unroll
    for (int u = 0; u < UNROLL; ++u)
        buf[u] = (u < T) ? __ldcs(Ip + (size_t)u * N4) : make_float4(0.f,0.f,0.f,0.f);

    for (int t = 0; t < Tm; t += UNROLL) {
        // prefetch next group (guarded only near the end)
        float4 nbuf[UNROLL];
        #pragma unroll
        for (int u = 0; u < UNROLL; ++u) {
            int tt = t + UNROLL + u;
            nbuf[u] = (tt < T) ? __ldcs(Ip + (size_t)tt * N4)
                               : make_float4(0.f,0.f,0.f,0.f);
        }

        #pragma unroll
        for (int u = 0; u < UNROLL; ++u) {
            float4 It = buf[u];
            float4 ov;
            adex_step(It.x, vv[0], cc[0], rr[0], ov.x);
            adex_step(It.y, vv[1], cc[1], rr[1], ov.y);
            adex_step(It.z, vv[2], cc[2], rr[2], ov.z);
            adex_step(It.w, vv[3], cc[3], rr[3], ov.w);
            __stcs(Op + (size_t)(t + u) * N4, ov);
        }

        #pragma unroll
        for (int u = 0; u < UNROLL; ++u) buf[u] = nbuf[u];
    }

    // tail timesteps (buf already holds rows Tm..Tm+UNROLL-1, guarded)
    for (int u = 0; u < T - Tm; ++u) {
        float4 It = buf[u];
        float4 ov;
        adex_step(It.x, vv[0], cc[0], rr[0], ov.x);
        adex_step(It.y, vv[1], cc[1], rr[1], ov.y);
        adex_step(It.z, vv[2], cc[2], rr[2], ov.z);
        adex_step(It.w, vv[3], cc[3], rr[3], ov.w);
        __stcs(Op + (size_t)(Tm + u) * N4, ov);
    }
}

// scalar kernel for N % 4 remainder neurons
__global__ void adex_scalar_kernel(
    const float* __restrict__ I, const float* __restrict__ v0,
    const float* __restrict__ c0, const int* __restrict__ ref0,
    float* __restrict__ out, int T, int N, int n0)
{
    int n = n0 + blockIdx.x * blockDim.x + threadIdx.x;
    if (n >= N) return;
    float v = v0[n], c = c0[n];
    int ref = ref0[n];
    for (int t = 0; t < T; ++t) {
        float ov;
        adex_step(I[(size_t)t * N + n], v, c, ref, ov);
        out[(size_t)t * N + n] = ov;
    }
}

extern "C" void kernel_launch(void* const* d_in, const int* in_sizes, int n_in,
                              void* d_out, int out_size)
{
    const float* I    = (const float*)d_in[0];
    const float* v0   = (const float*)d_in[1];
    const float* c0   = (const float*)d_in[2];
    const int*   ref0 = (const int*)  d_in[3];
    float*       out  = (float*)d_out;

    int N = in_sizes[1];
    int T = in_sizes[0] / N;

    int N4  = N / 4;
    int rem = N - N4 * 4;

    if (N4 > 0 && rem == 0) {
        int threads = 64;
        int blocks  = (N4 + threads - 1) / threads;
        adex_vec4_kernel<<<blocks, threads>>>(
            (const float4*)I, (const float4*)v0, (const float4*)c0,
            (const int4*)ref0, (float4*)out, T, N4);
    } else {
        // fallback path: N not divisible by 4 -> vector part + scalar tail
        if (N4 > 0) {
            int threads = 64;
            int blocks  = (N4 + threads - 1) / threads;
            adex_vec4_kernel<<<blocks, threads>>>(
                (const float4*)I, (const float4*)v0, (const float4*)c0,
                (const int4*)ref0, (float4*)out, T, N4);
            // NOTE: vector kernel strides rows by N4 float4 = N floats only
            // when rem==0; with rem>0 row stride differs, so instead run all
            // neurons through the scalar kernel for correctness.
        }
        if (rem > 0 || N4 == 0) {
            int threads = 256;
            int blocks  = (N + threads - 1) / threads;
            adex_scalar_kernel<<<blocks, threads>>>(I, v0, c0, ref0, out, T, N, 0);
        }
    }
}

// round 3
// speedup vs baseline: 1.4517x; 1.4517x over previous
#include <cuda_runtime.h>
#include <cuda_bf16.h>

// AdEx neuron sim, sm_103a. Round 3.
// 1 neuron/thread (100k threads = ~21 warps/SM), T-loop in-kernel.
// exp term in 4 instr: FADD (cancellation-free v-VT), FMNMX clip, FFMA fold, MUFU.EX2.
// Single-buffer UNROLL=8 prefetch pipeline (reload slot in place; no copy MOVs).

#define UNROLL 8

// ---- folded constants ----
#define C_EL        (-70.6e-3f)
#define C_VT        (-50.4e-3f)
#define C_CLIP      (0.03f)                     // 15 * DELTAT  (clip before scaling)
#define C_SLOPE     (721.3475204444817f)        // (1/DELTAT) * log2(e)
#define C_LOG2KE    (-12.193609594800305f)      // log2(DT/CM * GL * DELTAT)
#define C_DTCM      (3558718.8612099644f)       // DT/CM
#define C_A1        (0.8932384341637011f)       // 1 - (DT/CM)*GL
#define C_CADD      (-0.007537366634842701f)    // (DT/CM)*GL*EL
#define C_CC        (0.9930555555555556f)       // 1 - DT/TAUW
#define C_CA        (2.7777777777777776e-11f)   // (DT/TAUW)*A
#define C_CB        (1.961111111111111e-12f)    // -(DT/TAUW)*A*EL
#define C_B         (0.0805e-9f)
#define C_REFSTEPS  2

__device__ __forceinline__ void adex_step(float It, float& v, float& c, int& ref,
                                          float& v_out) {
    bool  in_ref = ref > 0;
    float v_eff  = in_ref ? C_EL : v;

    // E = (DT/CM)*GL*DELTAT * exp(min((v_eff-VT)/DELTAT, 15))
    float d   = v_eff - C_VT;                  // near-exact (same-magnitude sub)
    float dc  = fminf(d, C_CLIP);
    float y   = fmaf(dc, C_SLOPE, C_LOG2KE);
    float E;
    asm("ex2.approx.ftz.f32 %0, %1;" : "=f"(E) : "f"(y));

    // v_new = A1*v_eff + CADD + DTCM*(It - c) + E
    float q1 = fmaf(C_DTCM, It, E);
    float q2 = fmaf(-C_DTCM, c, q1);
    float v_new = fmaf(C_A1, v_eff, q2 + C_CADD);
    v_new = in_ref ? C_EL : v_new;

    // c_new = CC*c + CA*v_eff + CB
    float c_new = fmaf(C_CC, c, fmaf(C_CA, v_eff, C_CB));

    bool spike = v_new >= C_VT;
    v   = spike ? C_EL : v_new;
    c   = spike ? (c_new + C_B) : c_new;
    ref = spike ? C_REFSTEPS : max(ref - 1, 0);
    v_out = v;
}

__global__ void __launch_bounds__(256) adex_kernel(
    const float* __restrict__ I,    // [T, N]
    const float* __restrict__ v0,
    const float* __restrict__ c0,
    const int*   __restrict__ ref0,
    float*       __restrict__ out,  // [T, N]
    int T, int N)
{
    int n = blockIdx.x * blockDim.x + threadIdx.x;
    if (n >= N) return;

    float v   = v0[n];
    float c   = c0[n];
    int   ref = ref0[n];

    const float* Ip = I + n;
    float*       Op = out + n;

    // prime: rows 0..UNROLL-1
    float buf[UNROLL];
    #pragma unroll
    for (int u = 0; u < UNROLL; ++u)
        buf[u] = (u < T) ? __ldcs(Ip + (size_t)u * N) : 0.0f;

    int Tm = (T / UNROLL) * UNROLL;

    for (int t = 0; t < Tm; t += UNROLL) {
        #pragma unroll
        for (int u = 0; u < UNROLL; ++u) {
            float It = buf[u];
            // reload this slot with row t+UNROLL+u (latency covered by the
            // remaining steps of this group + next group)
            int tt = t + UNROLL + u;
            if (tt < T) buf[u] = __ldcs(Ip + (size_t)tt * N);

            float ov;
            adex_step(It, v, c, ref, ov);
            __stcs(Op + (size_t)(t + u) * N, ov);
        }
    }

    // tail rows Tm..T-1 (already resident in buf[0..T-Tm-1])
    #pragma unroll
    for (int u = 0; u < UNROLL; ++u) {
        if (Tm + u < T) {
            float ov;
            adex_step(buf[u], v, c, ref, ov);
            __stcs(Op + (size_t)(Tm + u) * N, ov);
        }
    }
}

extern "C" void kernel_launch(void* const* d_in, const int* in_sizes, int n_in,
                              void* d_out, int out_size)
{
    const float* I    = (const float*)d_in[0];
    const float* v0   = (const float*)d_in[1];
    const float* c0   = (const float*)d_in[2];
    const int*   ref0 = (const int*)  d_in[3];
    float*       out  = (float*)d_out;

    int N = in_sizes[1];
    int T = in_sizes[0] / N;

    int threads = 256;
    int blocks  = (N + threads - 1) / threads;
    adex_kernel<<<blocks, threads>>>(I, v0, c0, ref0, out, T, N);
}